// round 2
// baseline (speedup 1.0000x reference)
#include <cuda_runtime.h>
#include <cuda_bf16.h>
#include <stdint.h>

#define NNODE 50000
#define NEDGE 300000
#define DIM   256
#define FEATD 1024
#define NCLS  40

// ---------------- scratch (static device memory; no allocations) -------------
__device__ float g_bufA[(size_t)NNODE * DIM];   // current node features
__device__ float g_bufM[(size_t)NNODE * DIM];   // SpMM aggregation buffer
__device__ float g_norm_s[NNODE];
__device__ float g_norm_d[NNODE];
__device__ float g_deg_out[NNODE];
__device__ float g_deg_in[NNODE];
__device__ float g_sum[DIM];
__device__ float g_sumsq[DIM];
__device__ float g_scale[DIM];
__device__ float g_shift[DIM];

// ---------------- degree / norm --------------------------------------------
__global__ void k_degree(const int* __restrict__ src, const int* __restrict__ dst) {
    int e = blockIdx.x * blockDim.x + threadIdx.x;
    if (e < NEDGE) {
        atomicAdd(&g_deg_out[src[e]], 1.0f);
        atomicAdd(&g_deg_in[dst[e]], 1.0f);
    }
}

__global__ void k_norms() {
    int i = blockIdx.x * blockDim.x + threadIdx.x;
    if (i < NNODE) {
        g_norm_s[i] = rsqrtf(fmaxf(g_deg_out[i], 1.0f));
        g_norm_d[i] = rsqrtf(fmaxf(g_deg_in[i], 1.0f));
    }
}

// ---------------- SpMM: m[dst] += x[src] * norm_s[src] ----------------------
__global__ void k_spmm(const int* __restrict__ src, const int* __restrict__ dst,
                       const float* __restrict__ x, float* __restrict__ m) {
    int idx = blockIdx.x * blockDim.x + threadIdx.x;   // < NEDGE*64 (19.2M)
    if (idx >= NEDGE * 64) return;
    int e = idx >> 6;
    int c = idx & 63;
    int s = src[e];
    int d = dst[e];
    float ns = g_norm_s[s];
    float4 v = ((const float4*)x)[s * 64 + c];
    v.x *= ns; v.y *= ns; v.z *= ns; v.w *= ns;
    float4* p = ((float4*)m) + d * 64 + c;
    asm volatile("red.global.add.v4.f32 [%0], {%1,%2,%3,%4};"
                 :: "l"(p), "f"(v.x), "f"(v.y), "f"(v.z), "f"(v.w)
                 : "memory");
}

// ---------------- tensor-core GEMM (3x-split bf16 HMMA) ----------------------
// C[M,Ncol] = (A * rowscale?) @ B + bias.  A[M,K] rm, B[K,Ncol] rm.
// BM=BN=128, BK=32, 256 threads (8 warps, 2x4), warp tile 64x32.
// A/B split into bf16 hi + bf16 residual lo; C = AhBh + AhBl + AlBh (AlBl dropped,
// ~2^-18 relative -> fp32-class accuracy).
// smem holds fragments pre-packed in HMMA lane order: A frag load = 1x LDS.128,
// B frag load = 1x LDS.64, both conflict-free.

__device__ __forceinline__ void split_bf16x2(float x, float y, uint32_t& hi, uint32_t& lo) {
    __nv_bfloat162 h2 = __floats2bfloat162_rn(x, y);           // .x = low half = even-k
    float lx = x - __bfloat162float(h2.x);
    float ly = y - __bfloat162float(h2.y);
    __nv_bfloat162 l2 = __floats2bfloat162_rn(lx, ly);
    hi = *reinterpret_cast<uint32_t*>(&h2);
    lo = *reinterpret_cast<uint32_t*>(&l2);
}

#define MMA_BF16(d, a, b)                                                        \
    asm volatile("mma.sync.aligned.m16n8k16.row.col.f32.bf16.bf16.f32 "          \
                 "{%0,%1,%2,%3},{%4,%5,%6,%7},{%8,%9},{%0,%1,%2,%3};"            \
                 : "+f"(d[0]), "+f"(d[1]), "+f"(d[2]), "+f"(d[3])                 \
                 : "r"(a[0]), "r"(a[1]), "r"(a[2]), "r"(a[3]), "r"(b[0]), "r"(b[1]))

__global__ __launch_bounds__(256) void k_mma_gemm(
    const float* __restrict__ A, const float* __restrict__ B,
    const float* __restrict__ bias, const float* __restrict__ rowscale,
    float* __restrict__ C, int M, int Ncol, int K)
{
    // fragment-major smem: [k16][tile][word]
    __shared__ uint32_t sAhi[2][8][128];
    __shared__ uint32_t sAlo[2][8][128];
    __shared__ uint32_t sBhi[2][16][64];
    __shared__ uint32_t sBlo[2][16][64];

    const int t = threadIdx.x;
    const int lane = t & 31;
    const int warp = t >> 5;
    const int wm = warp >> 2;        // 0..1
    const int wn = warp & 3;         // 0..3
    const int rowBase = blockIdx.y * 128;
    const int colBase = blockIdx.x * 128;

    float acc[4][4][4];
    #pragma unroll
    for (int i = 0; i < 4; i++)
        #pragma unroll
        for (int j = 0; j < 4; j++)
            #pragma unroll
            for (int r = 0; r < 4; r++) acc[i][j][r] = 0.0f;

    for (int k0 = 0; k0 < K; k0 += 32) {
        // ---- load A tile (128x32) -> fragment-major hi/lo ----
        #pragma unroll
        for (int j = 0; j < 8; j++) {
            int idx = t + 256 * j;        // 0..2047
            int row = idx >> 4;           // 0..127
            int kp  = idx & 15;           // k-pair 0..15
            int grow = rowBase + row;
            float2 v = make_float2(0.f, 0.f);
            if (grow < M) {
                v = *(const float2*)(A + (size_t)grow * K + k0 + kp * 2);
                if (rowscale) { float rs = rowscale[grow]; v.x *= rs; v.y *= rs; }
            }
            uint32_t hi, lo;
            split_bf16x2(v.x, v.y, hi, lo);
            int k16 = kp >> 3;
            int tg  = kp & 3;
            int reg = ((row & 15) >= 8 ? 1 : 0) + ((kp & 7) >= 4 ? 2 : 0);
            int mt  = row >> 4;
            int w   = ((row & 7) * 4 + tg) * 4 + reg;
            sAhi[k16][mt][w] = hi;
            sAlo[k16][mt][w] = lo;
        }
        // ---- load B tile (32x128) -> fragment-major hi/lo ----
        #pragma unroll
        for (int u = 0; u < 2; u++) {
            int q  = t + 256 * u;         // 0..511
            int kp = q >> 5;              // 0..15
            int n4 = q & 31;              // 0..31
            const float* bp = B + (size_t)(k0 + kp * 2) * Ncol + colBase + n4 * 4;
            float4 v0 = *(const float4*)bp;
            float4 v1 = *(const float4*)(bp + Ncol);
            int k16 = kp >> 3;
            int tg  = kp & 3;
            int regb = ((kp & 7) >= 4) ? 1 : 0;
            float e0[4] = {v0.x, v0.y, v0.z, v0.w};
            float e1[4] = {v1.x, v1.y, v1.z, v1.w};
            #pragma unroll
            for (int c = 0; c < 4; c++) {
                int n   = n4 * 4 + c;
                int gid = n & 7;
                int nt  = n >> 3;
                uint32_t hi, lo;
                split_bf16x2(e0[c], e1[c], hi, lo);   // low half = k-even
                int w = (gid * 4 + tg) * 2 + regb;
                sBhi[k16][nt][w] = hi;
                sBlo[k16][nt][w] = lo;
            }
        }
        __syncthreads();

        // ---- compute ----
        #pragma unroll
        for (int k16 = 0; k16 < 2; k16++) {
            uint32_t ah[4][4], al[4][4], bh[4][2], bl[4][2];
            #pragma unroll
            for (int i = 0; i < 4; i++) {
                uint4 h = *(const uint4*)&sAhi[k16][wm * 4 + i][lane * 4];
                ah[i][0] = h.x; ah[i][1] = h.y; ah[i][2] = h.z; ah[i][3] = h.w;
                uint4 l = *(const uint4*)&sAlo[k16][wm * 4 + i][lane * 4];
                al[i][0] = l.x; al[i][1] = l.y; al[i][2] = l.z; al[i][3] = l.w;
            }
            #pragma unroll
            for (int j = 0; j < 4; j++) {
                uint2 h = *(const uint2*)&sBhi[k16][wn * 4 + j][lane * 2];
                bh[j][0] = h.x; bh[j][1] = h.y;
                uint2 l = *(const uint2*)&sBlo[k16][wn * 4 + j][lane * 2];
                bl[j][0] = l.x; bl[j][1] = l.y;
            }
            #pragma unroll
            for (int i = 0; i < 4; i++)
                #pragma unroll
                for (int j = 0; j < 4; j++) {
                    MMA_BF16(acc[i][j], ah[i], bh[j]);
                    MMA_BF16(acc[i][j], ah[i], bl[j]);
                    MMA_BF16(acc[i][j], al[i], bh[j]);
                }
        }
        __syncthreads();
    }

    // ---- epilogue: + bias, store ----
    const int gid = lane >> 2;
    const int tg  = lane & 3;
    #pragma unroll
    for (int i = 0; i < 4; i++) {
        int r0 = rowBase + wm * 64 + i * 16 + gid;
        #pragma unroll
        for (int j = 0; j < 4; j++) {
            int col = colBase + wn * 32 + j * 8 + tg * 2;
            float2 b2 = *(const float2*)(bias + col);
            if (r0 < M) {
                float2 o = make_float2(acc[i][j][0] + b2.x, acc[i][j][1] + b2.y);
                *(float2*)(C + (size_t)r0 * Ncol + col) = o;
            }
            if (r0 + 8 < M) {
                float2 o = make_float2(acc[i][j][2] + b2.x, acc[i][j][3] + b2.y);
                *(float2*)(C + (size_t)(r0 + 8) * Ncol + col) = o;
            }
        }
    }
}

// ---------------- batchnorm stats + finalize + fused bn/elu -----------------
__global__ void k_bnstats(const float* __restrict__ x) {
    int c = threadIdx.x;
    float s = 0.0f, sq = 0.0f;
    for (int r = blockIdx.x; r < NNODE; r += gridDim.x) {
        float v = x[(size_t)r * DIM + c];
        s += v;
        sq += v * v;
    }
    atomicAdd(&g_sum[c], s);
    atomicAdd(&g_sumsq[c], sq);
}

__global__ void k_bnfin(const float* __restrict__ gamma, const float* __restrict__ beta) {
    int c = threadIdx.x;
    float invN = 1.0f / (float)NNODE;
    float mean = g_sum[c] * invN;
    float var  = g_sumsq[c] * invN - mean * mean;
    float sc = gamma[c] * rsqrtf(var + 1e-5f);
    g_scale[c] = sc;
    g_shift[c] = beta[c] - mean * sc;
}

__global__ void k_bnelu(float* __restrict__ x) {
    int idx = blockIdx.x * blockDim.x + threadIdx.x;   // < NNODE*64
    if (idx >= NNODE * 64) return;
    int c4 = idx & 63;
    float4 v = ((float4*)x)[idx];
    float4 sc = ((const float4*)g_scale)[c4];
    float4 sh = ((const float4*)g_shift)[c4];
    float y0 = fmaf(v.x, sc.x, sh.x);
    float y1 = fmaf(v.y, sc.y, sh.y);
    float y2 = fmaf(v.z, sc.z, sh.z);
    float y3 = fmaf(v.w, sc.w, sh.w);
    v.x = y0 > 0.f ? y0 : expm1f(y0);
    v.y = y1 > 0.f ? y1 : expm1f(y1);
    v.z = y2 > 0.f ? y2 : expm1f(y2);
    v.w = y3 > 0.f ? y3 : expm1f(y3);
    ((float4*)x)[idx] = v;
}

// ---------------- logits: out[N,40] = x[N,256] @ W[256,40] + b --------------
__global__ __launch_bounds__(256) void k_logits(
    const float* __restrict__ x, const float* __restrict__ W,
    const float* __restrict__ b, float* __restrict__ out)
{
    __shared__ float Ws[DIM * NCLS];
    __shared__ float bsh[NCLS];
    int tid = threadIdx.x;
    for (int i = tid; i < DIM * NCLS; i += 256) Ws[i] = W[i];
    if (tid < NCLS) bsh[tid] = b[tid];
    __syncthreads();

    int warp = tid >> 5;
    int lane = tid & 31;
    int c1 = (lane < 8) ? lane + 32 : lane;

    for (int r = blockIdx.x * 8 + warp; r < NNODE; r += gridDim.x * 8) {
        const float* xr = x + (size_t)r * DIM;
        float acc0 = 0.0f, acc1 = 0.0f;
        #pragma unroll 8
        for (int k = 0; k < DIM; k++) {
            float xv = __ldg(xr + k);
            acc0 = fmaf(xv, Ws[k * NCLS + lane], acc0);
            acc1 = fmaf(xv, Ws[k * NCLS + c1], acc1);
        }
        out[(size_t)r * NCLS + lane] = acc0 + bsh[lane];
        if (lane < 8)
            out[(size_t)r * NCLS + lane + 32] = acc1 + bsh[lane + 32];
    }
}

// ---------------- launch ----------------------------------------------------
extern "C" void kernel_launch(void* const* d_in, const int* in_sizes, int n_in,
                              void* d_out, int out_size) {
    const float* feat  = (const float*)d_in[0];
    const int*   src   = (const int*)  d_in[1];
    const int*   dst   = (const int*)  d_in[2];
    const float* W_fc  = (const float*)d_in[3];
    const float* b_fc  = (const float*)d_in[4];
    const float* W1    = (const float*)d_in[5];
    const float* b1    = (const float*)d_in[6];
    const float* W2    = (const float*)d_in[7];
    const float* b2    = (const float*)d_in[8];
    const float* W3    = (const float*)d_in[9];
    const float* b3    = (const float*)d_in[10];
    const float* gamma = (const float*)d_in[11];
    const float* beta  = (const float*)d_in[12];
    const float* W_lin = (const float*)d_in[13];
    const float* b_lin = (const float*)d_in[14];

    float* out  = (float*)d_out;
    float* outX = out;                            // [N, 256]
    float* outL = out + (size_t)NNODE * DIM;      // [N, 40]

    float *bufA, *bufM, *norm_d, *deg_out, *deg_in, *sum, *sumsq;
    cudaGetSymbolAddress((void**)&bufA,    g_bufA);
    cudaGetSymbolAddress((void**)&bufM,    g_bufM);
    cudaGetSymbolAddress((void**)&norm_d,  g_norm_d);
    cudaGetSymbolAddress((void**)&deg_out, g_deg_out);
    cudaGetSymbolAddress((void**)&deg_in,  g_deg_in);
    cudaGetSymbolAddress((void**)&sum,     g_sum);
    cudaGetSymbolAddress((void**)&sumsq,   g_sumsq);

    // degrees & norms
    cudaMemsetAsync(deg_out, 0, NNODE * sizeof(float));
    cudaMemsetAsync(deg_in,  0, NNODE * sizeof(float));
    k_degree<<<(NEDGE + 255) / 256, 256>>>(src, dst);
    k_norms<<<(NNODE + 255) / 256, 256>>>();

    // x0 = feat @ W_fc + b_fc
    dim3 gemmGrid(DIM / 128, (NNODE + 127) / 128);
    k_mma_gemm<<<gemmGrid, 256>>>(feat, W_fc, b_fc, nullptr, bufA, NNODE, DIM, FEATD);

    const float* Ws[3] = {W1, W2, W3};
    const float* bs[3] = {b1, b2, b3};

    for (int l = 0; l < 3; l++) {
        // m = segment_sum((x * norm_s)[src], dst)
        cudaMemsetAsync(bufM, 0, (size_t)NNODE * DIM * sizeof(float));
        k_spmm<<<(NEDGE * 64 + 255) / 256, 256>>>(src, dst, bufA, bufM);

        // x' = (m * norm_d) @ W + b
        float* dstBuf = (l == 2) ? outX : bufA;
        k_mma_gemm<<<gemmGrid, 256>>>(bufM, Ws[l], bs[l], norm_d, dstBuf, NNODE, DIM, DIM);

        if (l < 2) {
            cudaMemsetAsync(sum,   0, DIM * sizeof(float));
            cudaMemsetAsync(sumsq, 0, DIM * sizeof(float));
            k_bnstats<<<512, 256>>>(bufA);
            k_bnfin<<<1, 256>>>(gamma, beta);
            k_bnelu<<<(NNODE * 64 + 255) / 256, 256>>>(bufA);
        }
    }

    // logits = x3 @ W_lin + b_lin
    k_logits<<<1024, 256>>>(outX, W_lin, b_lin, outL);
}

// round 5
// speedup vs baseline: 1.8701x; 1.8701x over previous
#include <cuda_runtime.h>
#include <cuda_bf16.h>
#include <stdint.h>

#define NNODE 50000
#define NEDGE 300000
#define DIM   256
#define FEATD 1024
#define NCLS  40
#define RT    391          // row tiles = ceil(NNODE/128)

// ---------------- scratch (static device memory; no allocations) -------------
__device__ float g_bufA[(size_t)NNODE * DIM];
__device__ float g_bufM[(size_t)NNODE * DIM];
__device__ uint32_t g_Ahi[(size_t)RT * (FEATD / 32) * 2048];
__device__ uint32_t g_Alo[(size_t)RT * (FEATD / 32) * 2048];
__device__ uint32_t g_Bhi[131072 + 3 * 32768];
__device__ uint32_t g_Blo[131072 + 3 * 32768];
__device__ float g_norm_s[NNODE];
__device__ float g_norm_d[NNODE];
__device__ float g_deg_out[NNODE];
__device__ float g_deg_in[NNODE];
__device__ float g_sum[DIM];
__device__ float g_sumsq[DIM];
__device__ float g_scale[DIM];
__device__ float g_shift[DIM];

// ---------------- degree / norm --------------------------------------------
__global__ void k_degree(const int* __restrict__ src, const int* __restrict__ dst) {
    int e = blockIdx.x * blockDim.x + threadIdx.x;
    if (e < NEDGE) {
        atomicAdd(&g_deg_out[src[e]], 1.0f);
        atomicAdd(&g_deg_in[dst[e]], 1.0f);
    }
}

__global__ void k_norms() {
    int i = blockIdx.x * blockDim.x + threadIdx.x;
    if (i < NNODE) {
        g_norm_s[i] = rsqrtf(fmaxf(g_deg_out[i], 1.0f));
        g_norm_d[i] = rsqrtf(fmaxf(g_deg_in[i], 1.0f));
    }
}

// ---------------- SpMM: m[dst] += x[src] * norm_s[src] ----------------------
__global__ void k_spmm(const int* __restrict__ src, const int* __restrict__ dst,
                       const float* __restrict__ x, float* __restrict__ m) {
    int idx = blockIdx.x * blockDim.x + threadIdx.x;
    if (idx >= NEDGE * 64) return;
    int e = idx >> 6;
    int c = idx & 63;
    int s = src[e];
    int d = dst[e];
    float ns = g_norm_s[s];
    float4 v = ((const float4*)x)[s * 64 + c];
    v.x *= ns; v.y *= ns; v.z *= ns; v.w *= ns;
    float4* p = ((float4*)m) + d * 64 + c;
    asm volatile("red.global.add.v4.f32 [%0], {%1,%2,%3,%4};"
                 :: "l"(p), "f"(v.x), "f"(v.y), "f"(v.z), "f"(v.w)
                 : "memory");
}

// ---------------- bf16 split helpers ----------------------------------------
__device__ __forceinline__ void split_bf16x2(float x, float y, uint32_t& hi, uint32_t& lo) {
    __nv_bfloat162 h2 = __floats2bfloat162_rn(x, y);   // .x = even k (low half)
    float lx = x - __bfloat162float(h2.x);
    float ly = y - __bfloat162float(h2.y);
    __nv_bfloat162 l2 = __floats2bfloat162_rn(lx, ly);
    hi = *reinterpret_cast<uint32_t*>(&h2);
    lo = *reinterpret_cast<uint32_t*>(&l2);
}

// ---------------- conversion: A[M,K] f32 -> fragment-major hi/lo ------------
// idx = ((rowTile*(K/32)+k0)*2 + k16)*1024 + mt*128 + w
// w = r7*16 + tg*4 + reg ; reg bit0 -> row+8, reg bit1 -> k+4 within k16
__global__ void k_convA(const float* __restrict__ x, const float* __restrict__ rowscale,
                        uint32_t* __restrict__ hi, uint32_t* __restrict__ lo,
                        int M, int K, int k0shift, int total) {
    int idx = blockIdx.x * blockDim.x + threadIdx.x;
    if (idx >= total) return;
    int w   = idx & 127;
    int mt  = (idx >> 7) & 7;
    int k16 = (idx >> 10) & 1;
    int rest = idx >> 11;
    int k0 = rest & ((1 << k0shift) - 1);
    int rowTile = rest >> k0shift;
    int reg = w & 3;
    int tg  = (w >> 2) & 3;
    int r7  = w >> 4;
    int row = rowTile * 128 + mt * 16 + r7 + (reg & 1) * 8;
    int kp  = k16 * 8 + tg + ((reg >> 1) & 1) * 4;
    float2 v = make_float2(0.f, 0.f);
    if (row < M) {
        v = *(const float2*)(x + (size_t)row * K + k0 * 32 + kp * 2);
        if (rowscale) { float rs = rowscale[row]; v.x *= rs; v.y *= rs; }
    }
    uint32_t h, l;
    split_bf16x2(v.x, v.y, h, l);
    hi[idx] = h;
    lo[idx] = l;
}

// ---------------- conversion: B[K,Ncol] f32 -> fragment-major hi/lo ---------
// idx = ((colTile*(K/32)+k0)*2 + k16)*1024 + nt*64 + w ; w = gid*8 + tg*2 + regb
__global__ void k_convB(const float* __restrict__ B,
                        uint32_t* __restrict__ hi, uint32_t* __restrict__ lo,
                        int K, int Ncol, int k0shift, int total) {
    int idx = blockIdx.x * blockDim.x + threadIdx.x;
    if (idx >= total) return;
    int w   = idx & 63;
    int nt  = (idx >> 6) & 15;
    int k16 = (idx >> 10) & 1;
    int rest = idx >> 11;
    int k0 = rest & ((1 << k0shift) - 1);
    int colTile = rest >> k0shift;
    int regb = w & 1;
    int tg   = (w >> 1) & 3;
    int gid  = w >> 3;
    int n  = colTile * 128 + nt * 8 + gid;
    int kp = k16 * 8 + tg + 4 * regb;
    int krow = k0 * 32 + kp * 2;
    float v0 = B[(size_t)krow * Ncol + n];
    float v1 = B[(size_t)(krow + 1) * Ncol + n];
    uint32_t h, l;
    split_bf16x2(v0, v1, h, l);
    hi[idx] = h;
    lo[idx] = l;
}

// ---------------- tensor-core GEMM (3x-split bf16 HMMA, cp.async DB) --------
#define MMA_BF16(d, a, b)                                                        \
    asm volatile("mma.sync.aligned.m16n8k16.row.col.f32.bf16.bf16.f32 "          \
                 "{%0,%1,%2,%3},{%4,%5,%6,%7},{%8,%9},{%0,%1,%2,%3};"            \
                 : "+f"(d[0]), "+f"(d[1]), "+f"(d[2]), "+f"(d[3])                 \
                 : "r"(a[0]), "r"(a[1]), "r"(a[2]), "r"(a[3]), "r"(b[0]), "r"(b[1]))

__device__ __forceinline__ void cp16(uint32_t saddr, const void* gptr) {
    asm volatile("cp.async.cg.shared.global [%0], [%1], 16;" :: "r"(saddr), "l"(gptr));
}

extern __shared__ uint32_t smem_dyn[];

__global__ __launch_bounds__(256) void k_mma_gemm(
    const uint32_t* __restrict__ Ahi, const uint32_t* __restrict__ Alo,
    const uint32_t* __restrict__ Bhi, const uint32_t* __restrict__ Blo,
    const float* __restrict__ bias, float* __restrict__ C,
    int M, int Ncol, int K)
{
    const int t = threadIdx.x;
    const int lane = t & 31;
    const int warp = t >> 5;
    const int wm = warp >> 2;
    const int wn = warp & 3;
    const int rowTile = blockIdx.y;
    const int colTile = blockIdx.x;
    const int niter = K >> 5;

    uint32_t sbase = (uint32_t)__cvta_generic_to_shared(smem_dyn);

    auto load_tile = [&](int st, int i) {
        size_t aOff = ((size_t)(rowTile * niter + i)) * 2048;
        size_t bOff = ((size_t)(colTile * niter + i)) * 2048;
        uint32_t s = sbase + (uint32_t)st * 8192 * 4;
        #pragma unroll
        for (int j = 0; j < 2; j++) {
            int wofs = t * 4 + j * 1024;
            cp16(s + (0    + wofs) * 4, Ahi + aOff + wofs);
            cp16(s + (2048 + wofs) * 4, Alo + aOff + wofs);
            cp16(s + (4096 + wofs) * 4, Bhi + bOff + wofs);
            cp16(s + (6144 + wofs) * 4, Blo + bOff + wofs);
        }
        asm volatile("cp.async.commit_group;");
    };

    float acc[4][4][4];
    #pragma unroll
    for (int i = 0; i < 4; i++)
        #pragma unroll
        for (int j = 0; j < 4; j++)
            #pragma unroll
            for (int r = 0; r < 4; r++) acc[i][j][r] = 0.0f;

    load_tile(0, 0);

    for (int i = 0; i < niter; i++) {
        int st = i & 1;
        asm volatile("cp.async.wait_group 0;");
        __syncthreads();
        if (i + 1 < niter) load_tile(st ^ 1, i + 1);

        const uint32_t* pAhi = smem_dyn + st * 8192;
        const uint32_t* pAlo = pAhi + 2048;
        const uint32_t* pBhi = pAhi + 4096;
        const uint32_t* pBlo = pAhi + 6144;

        #pragma unroll
        for (int k16 = 0; k16 < 2; k16++) {
            uint32_t ah[4][4], al[4][4], bh[4][2], bl[4][2];
            #pragma unroll
            for (int i2 = 0; i2 < 4; i2++) {
                int o = k16 * 1024 + (wm * 4 + i2) * 128 + lane * 4;
                uint4 h = *(const uint4*)(pAhi + o);
                ah[i2][0] = h.x; ah[i2][1] = h.y; ah[i2][2] = h.z; ah[i2][3] = h.w;
                uint4 l = *(const uint4*)(pAlo + o);
                al[i2][0] = l.x; al[i2][1] = l.y; al[i2][2] = l.z; al[i2][3] = l.w;
            }
            #pragma unroll
            for (int j = 0; j < 4; j++) {
                int o = k16 * 1024 + (wn * 4 + j) * 64 + lane * 2;
                uint2 h = *(const uint2*)(pBhi + o);
                bh[j][0] = h.x; bh[j][1] = h.y;
                uint2 l = *(const uint2*)(pBlo + o);
                bl[j][0] = l.x; bl[j][1] = l.y;
            }
            #pragma unroll
            for (int i2 = 0; i2 < 4; i2++)
                #pragma unroll
                for (int j = 0; j < 4; j++) {
                    MMA_BF16(acc[i2][j], ah[i2], bh[j]);
                    MMA_BF16(acc[i2][j], ah[i2], bl[j]);
                    MMA_BF16(acc[i2][j], al[i2], bh[j]);
                }
        }
        __syncthreads();
    }

    const int gid = lane >> 2;
    const int tg  = lane & 3;
    const int rowBase = rowTile * 128;
    const int colBase = colTile * 128;
    #pragma unroll
    for (int i = 0; i < 4; i++) {
        int r0 = rowBase + wm * 64 + i * 16 + gid;
        #pragma unroll
        for (int j = 0; j < 4; j++) {
            int col = colBase + wn * 32 + j * 8 + tg * 2;
            float2 b2 = *(const float2*)(bias + col);
            if (r0 < M) {
                float2 o = make_float2(acc[i][j][0] + b2.x, acc[i][j][1] + b2.y);
                *(float2*)(C + (size_t)r0 * Ncol + col) = o;
            }
            if (r0 + 8 < M) {
                float2 o = make_float2(acc[i][j][2] + b2.x, acc[i][j][3] + b2.y);
                *(float2*)(C + (size_t)(r0 + 8) * Ncol + col) = o;
            }
        }
    }
}

// ---------------- batchnorm + elu -------------------------------------------
__global__ void k_bnstats(const float* __restrict__ x) {
    int c = threadIdx.x;
    float s = 0.0f, sq = 0.0f;
    for (int r = blockIdx.x; r < NNODE; r += gridDim.x) {
        float v = x[(size_t)r * DIM + c];
        s += v;
        sq += v * v;
    }
    atomicAdd(&g_sum[c], s);
    atomicAdd(&g_sumsq[c], sq);
}

__global__ void k_bnfin(const float* __restrict__ gamma, const float* __restrict__ beta) {
    int c = threadIdx.x;
    float invN = 1.0f / (float)NNODE;
    float mean = g_sum[c] * invN;
    float var  = g_sumsq[c] * invN - mean * mean;
    float sc = gamma[c] * rsqrtf(var + 1e-5f);
    g_scale[c] = sc;
    g_shift[c] = beta[c] - mean * sc;
}

__global__ void k_bnelu(float* __restrict__ x) {
    int idx = blockIdx.x * blockDim.x + threadIdx.x;
    if (idx >= NNODE * 64) return;
    int c4 = idx & 63;
    float4 v = ((float4*)x)[idx];
    float4 sc = ((const float4*)g_scale)[c4];
    float4 sh = ((const float4*)g_shift)[c4];
    float y0 = fmaf(v.x, sc.x, sh.x);
    float y1 = fmaf(v.y, sc.y, sh.y);
    float y2 = fmaf(v.z, sc.z, sh.z);
    float y3 = fmaf(v.w, sc.w, sh.w);
    v.x = y0 > 0.f ? y0 : expm1f(y0);
    v.y = y1 > 0.f ? y1 : expm1f(y1);
    v.z = y2 > 0.f ? y2 : expm1f(y2);
    v.w = y3 > 0.f ? y3 : expm1f(y3);
    ((float4*)x)[idx] = v;
}

// ---------------- logits ----------------------------------------------------
__global__ __launch_bounds__(256) void k_logits(
    const float* __restrict__ x, const float* __restrict__ W,
    const float* __restrict__ b, float* __restrict__ out)
{
    __shared__ float Ws[DIM * NCLS];
    __shared__ float bsh[NCLS];
    int tid = threadIdx.x;
    for (int i = tid; i < DIM * NCLS; i += 256) Ws[i] = W[i];
    if (tid < NCLS) bsh[tid] = b[tid];
    __syncthreads();

    int warp = tid >> 5;
    int lane = tid & 31;
    int c1 = (lane < 8) ? lane + 32 : lane;

    for (int r = blockIdx.x * 8 + warp; r < NNODE; r += gridDim.x * 8) {
        const float* xr = x + (size_t)r * DIM;
        float acc0 = 0.0f, acc1 = 0.0f;
        #pragma unroll 8
        for (int k = 0; k < DIM; k++) {
            float xv = __ldg(xr + k);
            acc0 = fmaf(xv, Ws[k * NCLS + lane], acc0);
            acc1 = fmaf(xv, Ws[k * NCLS + c1], acc1);
        }
        out[(size_t)r * NCLS + lane] = acc0 + bsh[lane];
        if (lane < 8)
            out[(size_t)r * NCLS + lane + 32] = acc1 + bsh[lane + 32];
    }
}

// ---------------- launch ----------------------------------------------------
extern "C" void kernel_launch(void* const* d_in, const int* in_sizes, int n_in,
                              void* d_out, int out_size) {
    const float* feat  = (const float*)d_in[0];
    const int*   src   = (const int*)  d_in[1];
    const int*   dst   = (const int*)  d_in[2];
    const float* W_fc  = (const float*)d_in[3];
    const float* b_fc  = (const float*)d_in[4];
    const float* W1    = (const float*)d_in[5];
    const float* b1    = (const float*)d_in[6];
    const float* W2    = (const float*)d_in[7];
    const float* b2    = (const float*)d_in[8];
    const float* W3    = (const float*)d_in[9];
    const float* b3    = (const float*)d_in[10];
    const float* gamma = (const float*)d_in[11];
    const float* beta  = (const float*)d_in[12];
    const float* W_lin = (const float*)d_in[13];
    const float* b_lin = (const float*)d_in[14];

    float* out  = (float*)d_out;
    float* outX = out;
    float* outL = out + (size_t)NNODE * DIM;

    float *bufA, *bufM, *norm_d, *deg_out, *deg_in, *sum, *sumsq;
    uint32_t *Ahi, *Alo, *Bhi, *Blo;
    cudaGetSymbolAddress((void**)&bufA,    g_bufA);
    cudaGetSymbolAddress((void**)&bufM,    g_bufM);
    cudaGetSymbolAddress((void**)&norm_d,  g_norm_d);
    cudaGetSymbolAddress((void**)&deg_out, g_deg_out);
    cudaGetSymbolAddress((void**)&deg_in,  g_deg_in);
    cudaGetSymbolAddress((void**)&sum,     g_sum);
    cudaGetSymbolAddress((void**)&sumsq,   g_sumsq);
    cudaGetSymbolAddress((void**)&Ahi,     g_Ahi);
    cudaGetSymbolAddress((void**)&Alo,     g_Alo);
    cudaGetSymbolAddress((void**)&Bhi,     g_Bhi);
    cudaGetSymbolAddress((void**)&Blo,     g_Blo);

    cudaFuncSetAttribute(k_mma_gemm, cudaFuncAttributeMaxDynamicSharedMemorySize, 65536);

    // degrees & norms
    cudaMemsetAsync(deg_out, 0, NNODE * sizeof(float));
    cudaMemsetAsync(deg_in,  0, NNODE * sizeof(float));
    k_degree<<<(NEDGE + 255) / 256, 256>>>(src, dst);
    k_norms<<<(NNODE + 255) / 256, 256>>>();

    // weight conversions
    const int fcBW = 2 * 32 * 2048;
    const int lyBW = 2 * 8 * 2048;
    k_convB<<<fcBW / 256, 256>>>(W_fc, Bhi, Blo, FEATD, DIM, 5, fcBW);
    k_convB<<<lyBW / 256, 256>>>(W1, Bhi + fcBW,           Blo + fcBW,           DIM, DIM, 3, lyBW);
    k_convB<<<lyBW / 256, 256>>>(W2, Bhi + fcBW + lyBW,    Blo + fcBW + lyBW,    DIM, DIM, 3, lyBW);
    k_convB<<<lyBW / 256, 256>>>(W3, Bhi + fcBW + 2*lyBW,  Blo + fcBW + 2*lyBW,  DIM, DIM, 3, lyBW);

    // fc: x0 = feat @ W_fc + b_fc
    {
        int total = RT * 32 * 2048;
        k_convA<<<(total + 255) / 256, 256>>>(feat, nullptr, Ahi, Alo, NNODE, FEATD, 5, total);
        dim3 grid(DIM / 128, RT);
        k_mma_gemm<<<grid, 256, 65536>>>(Ahi, Alo, Bhi, Blo, b_fc, bufA, NNODE, DIM, FEATD);
    }

    const float* bs[3] = {b1, b2, b3};
    const int  bwOff[3] = {fcBW, fcBW + lyBW, fcBW + 2 * lyBW};

    for (int l = 0; l < 3; l++) {
        cudaMemsetAsync(bufM, 0, (size_t)NNODE * DIM * sizeof(float));
        k_spmm<<<(NEDGE * 64 + 255) / 256, 256>>>(src, dst, bufA, bufM);

        int total = RT * 8 * 2048;
        k_convA<<<(total + 255) / 256, 256>>>(bufM, norm_d, Ahi, Alo, NNODE, DIM, 3, total);
        float* dstBuf = (l == 2) ? outX : bufA;
        dim3 grid(DIM / 128, RT);
        k_mma_gemm<<<grid, 256, 65536>>>(Ahi, Alo, Bhi + bwOff[l], Blo + bwOff[l],
                                         bs[l], dstBuf, NNODE, DIM, DIM);

        if (l < 2) {
            cudaMemsetAsync(sum,   0, DIM * sizeof(float));
            cudaMemsetAsync(sumsq, 0, DIM * sizeof(float));
            k_bnstats<<<512, 256>>>(bufA);
            k_bnfin<<<1, 256>>>(gamma, beta);
            k_bnelu<<<(NNODE * 64 + 255) / 256, 256>>>(bufA);
        }
    }

    k_logits<<<1024, 256>>>(outX, W_lin, b_lin, outL);
}

// round 6
// speedup vs baseline: 2.0194x; 1.0799x over previous
#include <cuda_runtime.h>
#include <cuda_bf16.h>
#include <stdint.h>

#define NNODE 50000
#define NEDGE 300000
#define DIM   256
#define FEATD 1024
#define NCLS  40
#define RT    391          // row tiles = ceil(NNODE/128)

// ---------------- scratch (static device memory; no allocations) -------------
__device__ float g_bufA[(size_t)NNODE * DIM];
__device__ float g_bufM[(size_t)NNODE * DIM];
__device__ uint32_t g_Ahi[(size_t)RT * (FEATD / 32) * 2048];
__device__ uint32_t g_Alo[(size_t)RT * (FEATD / 32) * 2048];
__device__ uint32_t g_Bhi[131072 + 3 * 32768];
__device__ uint32_t g_Blo[131072 + 3 * 32768];
__device__ float g_norm_s[NNODE];
__device__ float g_norm_d[NNODE];
__device__ float g_deg_out[NNODE];
__device__ float g_deg_in[NNODE];
__device__ int   g_deg_i[NNODE];
__device__ int   g_rowptr[NNODE + 1];
__device__ int   g_cursor[NNODE];
__device__ int   g_eidx[NEDGE];          // src node per CSR slot
__device__ float g_sum[DIM];
__device__ float g_sumsq[DIM];
__device__ float g_scale[DIM];
__device__ float g_shift[DIM];

// ---------------- degree / norm --------------------------------------------
__global__ void k_degree(const int* __restrict__ src, const int* __restrict__ dst) {
    int e = blockIdx.x * blockDim.x + threadIdx.x;
    if (e < NEDGE) {
        atomicAdd(&g_deg_out[src[e]], 1.0f);
        atomicAdd(&g_deg_in[dst[e]], 1.0f);
        atomicAdd(&g_deg_i[dst[e]], 1);
    }
}

__global__ void k_norms() {
    int i = blockIdx.x * blockDim.x + threadIdx.x;
    if (i < NNODE) {
        g_norm_s[i] = rsqrtf(fmaxf(g_deg_out[i], 1.0f));
        g_norm_d[i] = rsqrtf(fmaxf(g_deg_in[i], 1.0f));
    }
}

// ---------------- CSR build -------------------------------------------------
// single block, 512 threads; thread t owns contiguous node range.
__global__ __launch_bounds__(512) void k_scan() {
    __shared__ int part[512];
    const int t = threadIdx.x;
    const int per = (NNODE + 511) / 512;   // 98
    int lo = t * per;
    int hi = min(lo + per, NNODE);
    int s = 0;
    for (int i = lo; i < hi; i++) s += g_deg_i[i];
    part[t] = s;
    __syncthreads();
    // inclusive scan of partials
    for (int off = 1; off < 512; off <<= 1) {
        int v = (t >= off) ? part[t - off] : 0;
        __syncthreads();
        part[t] += v;
        __syncthreads();
    }
    int base = (t == 0) ? 0 : part[t - 1];
    for (int i = lo; i < hi; i++) {
        g_rowptr[i] = base;
        base += g_deg_i[i];
    }
    if (t == 511) g_rowptr[NNODE] = base;
}

__global__ void k_fill(const int* __restrict__ src, const int* __restrict__ dst) {
    int e = blockIdx.x * blockDim.x + threadIdx.x;
    if (e < NEDGE) {
        int d = dst[e];
        int pos = g_rowptr[d] + atomicAdd(&g_cursor[d], 1);
        g_eidx[pos] = src[e];
    }
}

// ---------------- SpMM (CSR gather): m[n] = sum_{s in in(n)} x[s]*norm_s[s] -
__global__ __launch_bounds__(256) void k_spmm_csr(const float* __restrict__ x,
                                                  float* __restrict__ m) {
    int idx = blockIdx.x * blockDim.x + threadIdx.x;   // NNODE*64
    if (idx >= NNODE * 64) return;
    int n = idx >> 6;
    int c = idx & 63;
    int b = g_rowptr[n];
    int e = g_rowptr[n + 1];
    float4 acc = make_float4(0.f, 0.f, 0.f, 0.f);
    for (int p = b; p < e; p++) {
        int s = g_eidx[p];
        float ns = g_norm_s[s];
        float4 v = ((const float4*)x)[s * 64 + c];
        acc.x = fmaf(v.x, ns, acc.x);
        acc.y = fmaf(v.y, ns, acc.y);
        acc.z = fmaf(v.z, ns, acc.z);
        acc.w = fmaf(v.w, ns, acc.w);
    }
    ((float4*)m)[n * 64 + c] = acc;
}

// ---------------- bf16 split helpers ----------------------------------------
__device__ __forceinline__ void split_bf16x2(float x, float y, uint32_t& hi, uint32_t& lo) {
    __nv_bfloat162 h2 = __floats2bfloat162_rn(x, y);   // .x = even k (low half)
    float lx = x - __bfloat162float(h2.x);
    float ly = y - __bfloat162float(h2.y);
    __nv_bfloat162 l2 = __floats2bfloat162_rn(lx, ly);
    hi = *reinterpret_cast<uint32_t*>(&h2);
    lo = *reinterpret_cast<uint32_t*>(&l2);
}

// ---------------- conversion: A[M,K] f32 -> fragment-major hi/lo ------------
__global__ void k_convA(const float* __restrict__ x, const float* __restrict__ rowscale,
                        uint32_t* __restrict__ hi, uint32_t* __restrict__ lo,
                        int M, int K, int k0shift, int total) {
    int idx = blockIdx.x * blockDim.x + threadIdx.x;
    if (idx >= total) return;
    int w   = idx & 127;
    int mt  = (idx >> 7) & 7;
    int k16 = (idx >> 10) & 1;
    int rest = idx >> 11;
    int k0 = rest & ((1 << k0shift) - 1);
    int rowTile = rest >> k0shift;
    int reg = w & 3;
    int tg  = (w >> 2) & 3;
    int r7  = w >> 4;
    int row = rowTile * 128 + mt * 16 + r7 + (reg & 1) * 8;
    int kp  = k16 * 8 + tg + ((reg >> 1) & 1) * 4;
    float2 v = make_float2(0.f, 0.f);
    if (row < M) {
        v = *(const float2*)(x + (size_t)row * K + k0 * 32 + kp * 2);
        if (rowscale) { float rs = rowscale[row]; v.x *= rs; v.y *= rs; }
    }
    uint32_t h, l;
    split_bf16x2(v.x, v.y, h, l);
    hi[idx] = h;
    lo[idx] = l;
}

// ---------------- conversion: B[K,Ncol] f32 -> fragment-major hi/lo ---------
__global__ void k_convB(const float* __restrict__ B,
                        uint32_t* __restrict__ hi, uint32_t* __restrict__ lo,
                        int K, int Ncol, int k0shift, int total) {
    int idx = blockIdx.x * blockDim.x + threadIdx.x;
    if (idx >= total) return;
    int w   = idx & 63;
    int nt  = (idx >> 6) & 15;
    int k16 = (idx >> 10) & 1;
    int rest = idx >> 11;
    int k0 = rest & ((1 << k0shift) - 1);
    int colTile = rest >> k0shift;
    int regb = w & 1;
    int tg   = (w >> 1) & 3;
    int gid  = w >> 3;
    int n  = colTile * 128 + nt * 8 + gid;
    int kp = k16 * 8 + tg + 4 * regb;
    int krow = k0 * 32 + kp * 2;
    float v0 = B[(size_t)krow * Ncol + n];
    float v1 = B[(size_t)(krow + 1) * Ncol + n];
    uint32_t h, l;
    split_bf16x2(v0, v1, h, l);
    hi[idx] = h;
    lo[idx] = l;
}

// ---------------- tensor-core GEMM (3x-split bf16 HMMA, cp.async DB) --------
#define MMA_BF16(d, a, b)                                                        \
    asm volatile("mma.sync.aligned.m16n8k16.row.col.f32.bf16.bf16.f32 "          \
                 "{%0,%1,%2,%3},{%4,%5,%6,%7},{%8,%9},{%0,%1,%2,%3};"            \
                 : "+f"(d[0]), "+f"(d[1]), "+f"(d[2]), "+f"(d[3])                 \
                 : "r"(a[0]), "r"(a[1]), "r"(a[2]), "r"(a[3]), "r"(b[0]), "r"(b[1]))

__device__ __forceinline__ void cp16(uint32_t saddr, const void* gptr) {
    asm volatile("cp.async.cg.shared.global [%0], [%1], 16;" :: "r"(saddr), "l"(gptr));
}

extern __shared__ uint32_t smem_dyn[];

__global__ __launch_bounds__(256) void k_mma_gemm(
    const uint32_t* __restrict__ Ahi, const uint32_t* __restrict__ Alo,
    const uint32_t* __restrict__ Bhi, const uint32_t* __restrict__ Blo,
    const float* __restrict__ bias, float* __restrict__ C,
    int M, int Ncol, int K)
{
    const int t = threadIdx.x;
    const int lane = t & 31;
    const int warp = t >> 5;
    const int wm = warp >> 2;
    const int wn = warp & 3;
    const int rowTile = blockIdx.y;
    const int colTile = blockIdx.x;
    const int niter = K >> 5;

    uint32_t sbase = (uint32_t)__cvta_generic_to_shared(smem_dyn);

    auto load_tile = [&](int st, int i) {
        size_t aOff = ((size_t)(rowTile * niter + i)) * 2048;
        size_t bOff = ((size_t)(colTile * niter + i)) * 2048;
        uint32_t s = sbase + (uint32_t)st * 8192 * 4;
        #pragma unroll
        for (int j = 0; j < 2; j++) {
            int wofs = t * 4 + j * 1024;
            cp16(s + (0    + wofs) * 4, Ahi + aOff + wofs);
            cp16(s + (2048 + wofs) * 4, Alo + aOff + wofs);
            cp16(s + (4096 + wofs) * 4, Bhi + bOff + wofs);
            cp16(s + (6144 + wofs) * 4, Blo + bOff + wofs);
        }
        asm volatile("cp.async.commit_group;");
    };

    float acc[4][4][4];
    #pragma unroll
    for (int i = 0; i < 4; i++)
        #pragma unroll
        for (int j = 0; j < 4; j++)
            #pragma unroll
            for (int r = 0; r < 4; r++) acc[i][j][r] = 0.0f;

    load_tile(0, 0);

    for (int i = 0; i < niter; i++) {
        int st = i & 1;
        asm volatile("cp.async.wait_group 0;");
        __syncthreads();
        if (i + 1 < niter) load_tile(st ^ 1, i + 1);

        const uint32_t* pAhi = smem_dyn + st * 8192;
        const uint32_t* pAlo = pAhi + 2048;
        const uint32_t* pBhi = pAhi + 4096;
        const uint32_t* pBlo = pAhi + 6144;

        #pragma unroll
        for (int k16 = 0; k16 < 2; k16++) {
            uint32_t ah[4][4], al[4][4], bh[4][2], bl[4][2];
            #pragma unroll
            for (int i2 = 0; i2 < 4; i2++) {
                int o = k16 * 1024 + (wm * 4 + i2) * 128 + lane * 4;
                uint4 h = *(const uint4*)(pAhi + o);
                ah[i2][0] = h.x; ah[i2][1] = h.y; ah[i2][2] = h.z; ah[i2][3] = h.w;
                uint4 l = *(const uint4*)(pAlo + o);
                al[i2][0] = l.x; al[i2][1] = l.y; al[i2][2] = l.z; al[i2][3] = l.w;
            }
            #pragma unroll
            for (int j = 0; j < 4; j++) {
                int o = k16 * 1024 + (wn * 4 + j) * 64 + lane * 2;
                uint2 h = *(const uint2*)(pBhi + o);
                bh[j][0] = h.x; bh[j][1] = h.y;
                uint2 l = *(const uint2*)(pBlo + o);
                bl[j][0] = l.x; bl[j][1] = l.y;
            }
            #pragma unroll
            for (int i2 = 0; i2 < 4; i2++)
                #pragma unroll
                for (int j = 0; j < 4; j++) {
                    MMA_BF16(acc[i2][j], ah[i2], bh[j]);
                    MMA_BF16(acc[i2][j], ah[i2], bl[j]);
                    MMA_BF16(acc[i2][j], al[i2], bh[j]);
                }
        }
        __syncthreads();
    }

    const int gid = lane >> 2;
    const int tg  = lane & 3;
    const int rowBase = rowTile * 128;
    const int colBase = colTile * 128;
    #pragma unroll
    for (int i = 0; i < 4; i++) {
        int r0 = rowBase + wm * 64 + i * 16 + gid;
        #pragma unroll
        for (int j = 0; j < 4; j++) {
            int col = colBase + wn * 32 + j * 8 + tg * 2;
            float2 b2 = *(const float2*)(bias + col);
            if (r0 < M) {
                float2 o = make_float2(acc[i][j][0] + b2.x, acc[i][j][1] + b2.y);
                *(float2*)(C + (size_t)r0 * Ncol + col) = o;
            }
            if (r0 + 8 < M) {
                float2 o = make_float2(acc[i][j][2] + b2.x, acc[i][j][3] + b2.y);
                *(float2*)(C + (size_t)(r0 + 8) * Ncol + col) = o;
            }
        }
    }
}

// ---------------- batchnorm + elu -------------------------------------------
__global__ void k_bnstats(const float* __restrict__ x) {
    int c = threadIdx.x;
    float s = 0.0f, sq = 0.0f;
    for (int r = blockIdx.x; r < NNODE; r += gridDim.x) {
        float v = x[(size_t)r * DIM + c];
        s += v;
        sq += v * v;
    }
    atomicAdd(&g_sum[c], s);
    atomicAdd(&g_sumsq[c], sq);
}

__global__ void k_bnfin(const float* __restrict__ gamma, const float* __restrict__ beta) {
    int c = threadIdx.x;
    float invN = 1.0f / (float)NNODE;
    float mean = g_sum[c] * invN;
    float var  = g_sumsq[c] * invN - mean * mean;
    float sc = gamma[c] * rsqrtf(var + 1e-5f);
    g_scale[c] = sc;
    g_shift[c] = beta[c] - mean * sc;
}

__global__ void k_bnelu(float* __restrict__ x) {
    int idx = blockIdx.x * blockDim.x + threadIdx.x;
    if (idx >= NNODE * 64) return;
    int c4 = idx & 63;
    float4 v = ((float4*)x)[idx];
    float4 sc = ((const float4*)g_scale)[c4];
    float4 sh = ((const float4*)g_shift)[c4];
    float y0 = fmaf(v.x, sc.x, sh.x);
    float y1 = fmaf(v.y, sc.y, sh.y);
    float y2 = fmaf(v.z, sc.z, sh.z);
    float y3 = fmaf(v.w, sc.w, sh.w);
    v.x = y0 > 0.f ? y0 : expm1f(y0);
    v.y = y1 > 0.f ? y1 : expm1f(y1);
    v.z = y2 > 0.f ? y2 : expm1f(y2);
    v.w = y3 > 0.f ? y3 : expm1f(y3);
    ((float4*)x)[idx] = v;
}

// ---------------- logits ----------------------------------------------------
__global__ __launch_bounds__(256) void k_logits(
    const float* __restrict__ x, const float* __restrict__ W,
    const float* __restrict__ b, float* __restrict__ out)
{
    __shared__ float Ws[DIM * NCLS];
    __shared__ float bsh[NCLS];
    int tid = threadIdx.x;
    for (int i = tid; i < DIM * NCLS; i += 256) Ws[i] = W[i];
    if (tid < NCLS) bsh[tid] = b[tid];
    __syncthreads();

    int warp = tid >> 5;
    int lane = tid & 31;
    int c1 = (lane < 8) ? lane + 32 : lane;

    for (int r = blockIdx.x * 8 + warp; r < NNODE; r += gridDim.x * 8) {
        const float* xr = x + (size_t)r * DIM;
        float acc0 = 0.0f, acc1 = 0.0f;
        #pragma unroll 8
        for (int k = 0; k < DIM; k++) {
            float xv = __ldg(xr + k);
            acc0 = fmaf(xv, Ws[k * NCLS + lane], acc0);
            acc1 = fmaf(xv, Ws[k * NCLS + c1], acc1);
        }
        out[(size_t)r * NCLS + lane] = acc0 + bsh[lane];
        if (lane < 8)
            out[(size_t)r * NCLS + lane + 32] = acc1 + bsh[lane + 32];
    }
}

// ---------------- launch ----------------------------------------------------
extern "C" void kernel_launch(void* const* d_in, const int* in_sizes, int n_in,
                              void* d_out, int out_size) {
    const float* feat  = (const float*)d_in[0];
    const int*   src   = (const int*)  d_in[1];
    const int*   dst   = (const int*)  d_in[2];
    const float* W_fc  = (const float*)d_in[3];
    const float* b_fc  = (const float*)d_in[4];
    const float* W1    = (const float*)d_in[5];
    const float* b1    = (const float*)d_in[6];
    const float* W2    = (const float*)d_in[7];
    const float* b2    = (const float*)d_in[8];
    const float* W3    = (const float*)d_in[9];
    const float* b3    = (const float*)d_in[10];
    const float* gamma = (const float*)d_in[11];
    const float* beta  = (const float*)d_in[12];
    const float* W_lin = (const float*)d_in[13];
    const float* b_lin = (const float*)d_in[14];

    float* out  = (float*)d_out;
    float* outX = out;
    float* outL = out + (size_t)NNODE * DIM;

    float *bufA, *bufM, *norm_d, *deg_out, *deg_in, *sum, *sumsq;
    uint32_t *Ahi, *Alo, *Bhi, *Blo;
    int *deg_i, *cursor;
    cudaGetSymbolAddress((void**)&bufA,    g_bufA);
    cudaGetSymbolAddress((void**)&bufM,    g_bufM);
    cudaGetSymbolAddress((void**)&norm_d,  g_norm_d);
    cudaGetSymbolAddress((void**)&deg_out, g_deg_out);
    cudaGetSymbolAddress((void**)&deg_in,  g_deg_in);
    cudaGetSymbolAddress((void**)&sum,     g_sum);
    cudaGetSymbolAddress((void**)&sumsq,   g_sumsq);
    cudaGetSymbolAddress((void**)&Ahi,     g_Ahi);
    cudaGetSymbolAddress((void**)&Alo,     g_Alo);
    cudaGetSymbolAddress((void**)&Bhi,     g_Bhi);
    cudaGetSymbolAddress((void**)&Blo,     g_Blo);
    cudaGetSymbolAddress((void**)&deg_i,   g_deg_i);
    cudaGetSymbolAddress((void**)&cursor,  g_cursor);

    cudaFuncSetAttribute(k_mma_gemm, cudaFuncAttributeMaxDynamicSharedMemorySize, 65536);

    // degrees, norms, CSR
    cudaMemsetAsync(deg_out, 0, NNODE * sizeof(float));
    cudaMemsetAsync(deg_in,  0, NNODE * sizeof(float));
    cudaMemsetAsync(deg_i,   0, NNODE * sizeof(int));
    cudaMemsetAsync(cursor,  0, NNODE * sizeof(int));
    k_degree<<<(NEDGE + 255) / 256, 256>>>(src, dst);
    k_norms<<<(NNODE + 255) / 256, 256>>>();
    k_scan<<<1, 512>>>();
    k_fill<<<(NEDGE + 255) / 256, 256>>>(src, dst);

    // weight conversions
    const int fcBW = 2 * 32 * 2048;
    const int lyBW = 2 * 8 * 2048;
    k_convB<<<fcBW / 256, 256>>>(W_fc, Bhi, Blo, FEATD, DIM, 5, fcBW);
    k_convB<<<lyBW / 256, 256>>>(W1, Bhi + fcBW,           Blo + fcBW,           DIM, DIM, 3, lyBW);
    k_convB<<<lyBW / 256, 256>>>(W2, Bhi + fcBW + lyBW,    Blo + fcBW + lyBW,    DIM, DIM, 3, lyBW);
    k_convB<<<lyBW / 256, 256>>>(W3, Bhi + fcBW + 2*lyBW,  Blo + fcBW + 2*lyBW,  DIM, DIM, 3, lyBW);

    // fc: x0 = feat @ W_fc + b_fc
    {
        int total = RT * 32 * 2048;
        k_convA<<<(total + 255) / 256, 256>>>(feat, nullptr, Ahi, Alo, NNODE, FEATD, 5, total);
        dim3 grid(DIM / 128, RT);
        k_mma_gemm<<<grid, 256, 65536>>>(Ahi, Alo, Bhi, Blo, b_fc, bufA, NNODE, DIM, FEATD);
    }

    const float* bs[3] = {b1, b2, b3};
    const int  bwOff[3] = {fcBW, fcBW + lyBW, fcBW + 2 * lyBW};

    for (int l = 0; l < 3; l++) {
        k_spmm_csr<<<(NNODE * 64 + 255) / 256, 256>>>(bufA, bufM);

        int total = RT * 8 * 2048;
        k_convA<<<(total + 255) / 256, 256>>>(bufM, norm_d, Ahi, Alo, NNODE, DIM, 3, total);
        float* dstBuf = (l == 2) ? outX : bufA;
        dim3 grid(DIM / 128, RT);
        k_mma_gemm<<<grid, 256, 65536>>>(Ahi, Alo, Bhi + bwOff[l], Blo + bwOff[l],
                                         bs[l], dstBuf, NNODE, DIM, DIM);

        if (l < 2) {
            cudaMemsetAsync(sum,   0, DIM * sizeof(float));
            cudaMemsetAsync(sumsq, 0, DIM * sizeof(float));
            k_bnstats<<<512, 256>>>(bufA);
            k_bnfin<<<1, 256>>>(gamma, beta);
            k_bnelu<<<(NNODE * 64 + 255) / 256, 256>>>(bufA);
        }
    }

    k_logits<<<1024, 256>>>(outX, W_lin, b_lin, outL);
}